// round 2
// baseline (speedup 1.0000x reference)
#include <cuda_runtime.h>
#include <math.h>
#include <stdint.h>

#define B_  2
#define T_  2048
#define C_  1024
#define H_  16
#define D_  64
#define BH_ (B_*H_)     // 32
#define M_  (B_*T_)     // 4096
#define N3_ (3*C_)      // 3072

// Scratch (allocation-free rule: __device__ globals)
__device__ float g_q[BH_*T_*D_];
__device__ float g_k[BH_*T_*D_];
__device__ float g_v[BH_*T_*D_];
__device__ float g_y[M_*C_];
__device__ float g_cos[T_*(D_/2)];
__device__ float g_sin[T_*(D_/2)];

// ---------------------------------------------------------------------------
// RoPE table: cos/sin of fp32-rounded (t * inv_freq), trig done in fp64 so the
// argument reduction at angles up to 2047 rad is exact regardless of fast-math.
// ---------------------------------------------------------------------------
__global__ void rope_table_kernel() {
    int idx = blockIdx.x * 256 + threadIdx.x;   // 65536 = 2048*32
    int t = idx >> 5;
    int i = idx & 31;
    double inv = pow(10000.0, -(double)(2 * i) / 64.0);
    float ff = (float)t * (float)inv;           // match reference fp32 rounding
    double s, c;
    sincos((double)ff, &s, &c);
    g_cos[idx] = (float)c;
    g_sin[idx] = (float)s;
}

// ---------------------------------------------------------------------------
// QKV GEMM: x[4096,1024] @ w_qkv[1024,3072], epilogue scatters into
// q/k/v [B,H,T,D] with RoPE applied to q,k and 1/sqrt(D) folded into q.
// 128x128x16 tile, 256 threads, 8x8 micro-tile.
// ---------------------------------------------------------------------------
__global__ __launch_bounds__(256) void qkv_kernel(
    const float* __restrict__ A, const float* __restrict__ Bm)
{
    __shared__ float As[16][128];
    __shared__ float Bs[16][132];
    const int tid = threadIdx.x;
    const int tx = tid & 15, ty = tid >> 4;
    const int m0 = blockIdx.y * 128;
    const int n0 = blockIdx.x * 128;

    float acc[8][8] = {};

    for (int kk = 0; kk < C_; kk += 16) {
        #pragma unroll
        for (int s = tid; s < 512; s += 256) {
            int arow = s >> 2, ac4 = (s & 3) << 2;
            float4 v = *(const float4*)(A + (size_t)(m0 + arow) * C_ + kk + ac4);
            As[ac4 + 0][arow] = v.x; As[ac4 + 1][arow] = v.y;
            As[ac4 + 2][arow] = v.z; As[ac4 + 3][arow] = v.w;
        }
        #pragma unroll
        for (int s = tid; s < 512; s += 256) {
            int brow = s >> 5, bc4 = (s & 31) << 2;
            *(float4*)&Bs[brow][bc4] =
                *(const float4*)(Bm + (size_t)(kk + brow) * N3_ + n0 + bc4);
        }
        __syncthreads();
        #pragma unroll
        for (int k = 0; k < 16; k++) {
            float a[8], b[8];
            *(float4*)(a)     = *(const float4*)&As[k][ty * 8];
            *(float4*)(a + 4) = *(const float4*)&As[k][ty * 8 + 4];
            *(float4*)(b)     = *(const float4*)&Bs[k][tx * 8];
            *(float4*)(b + 4) = *(const float4*)&Bs[k][tx * 8 + 4];
            #pragma unroll
            for (int i = 0; i < 8; i++)
                #pragma unroll
                for (int j = 0; j < 8; j++)
                    acc[i][j] = fmaf(a[i], b[j], acc[i][j]);
        }
        __syncthreads();
    }

    // Epilogue: scatter + RoPE
    #pragma unroll
    for (int i = 0; i < 8; i++) {
        int m = m0 + ty * 8 + i;
        int b = m >> 11;
        int t = m & 2047;
        #pragma unroll
        for (int jp = 0; jp < 4; jp++) {
            int n = n0 + tx * 8 + jp * 2;
            int sec = n >> 10;
            int c = n & 1023;
            int h = c >> 6;
            int d = c & 63;                 // even
            float e = acc[i][jp * 2];
            float o = acc[i][jp * 2 + 1];
            size_t base = ((size_t)(b * H_ + h) * T_ + t) * D_ + d;
            if (sec == 2) {
                g_v[base] = e; g_v[base + 1] = o;
            } else {
                int fi = d >> 1;
                float co = g_cos[t * 32 + fi];
                float si = g_sin[t * 32 + fi];
                float oe = e * co - o * si;
                float oo = e * si + o * co;
                if (sec == 0) { g_q[base] = oe * 0.125f; g_q[base + 1] = oo * 0.125f; }
                else          { g_k[base] = oe;          g_k[base + 1] = oo;          }
            }
        }
    }
}

// ---------------------------------------------------------------------------
// Flash-style causal attention, fp32. 64 q-rows x 64 k-cols per block,
// 256 threads, 4x4 micro-tiles, online softmax. Heavy tiles scheduled first.
// ---------------------------------------------------------------------------
#define AS_ 65
#define ATTN_SMEM (4 * 64 * AS_ * (int)sizeof(float))  // 66560 B

__global__ __launch_bounds__(256) void attn_kernel() {
    extern __shared__ float sm[];
    float* Qs = sm;
    float* Ks = sm + 64 * AS_;
    float* Vs = sm + 2 * 64 * AS_;
    float* Ps = sm + 3 * 64 * AS_;

    const int tid = threadIdx.x;
    const int tx = tid & 15, ty = tid >> 4;
    const int qi = (int)gridDim.x - 1 - (int)blockIdx.x;   // heavy-first
    const int bh = blockIdx.y;
    const int b  = bh >> 4;
    const int h  = bh & 15;

    const float* Qg = g_q + ((size_t)bh * T_ + qi * 64) * D_;

    for (int idx = tid; idx < 64 * 64; idx += 256) {
        int r = idx >> 6, d = idx & 63;
        Qs[r * AS_ + d] = Qg[idx];
    }

    float o[4][4] = {};
    float mrow[4], lrow[4];
    #pragma unroll
    for (int i = 0; i < 4; i++) { mrow[i] = -1e30f; lrow[i] = 0.0f; }

    __syncthreads();

    for (int j = 0; j <= qi; j++) {
        const float* Kg = g_k + ((size_t)bh * T_ + j * 64) * D_;
        const float* Vg = g_v + ((size_t)bh * T_ + j * 64) * D_;
        for (int idx = tid; idx < 64 * 64; idx += 256) {
            int r = idx >> 6, d = idx & 63;
            Ks[r * AS_ + d] = Kg[idx];
            Vs[r * AS_ + d] = Vg[idx];
        }
        __syncthreads();

        // S = Q @ K^T  (4x4 per thread)
        float s[4][4] = {};
        #pragma unroll 8
        for (int d = 0; d < 64; d++) {
            float a[4], bb[4];
            #pragma unroll
            for (int i = 0; i < 4; i++) a[i]  = Qs[(ty * 4 + i) * AS_ + d];
            #pragma unroll
            for (int c = 0; c < 4; c++) bb[c] = Ks[(tx * 4 + c) * AS_ + d];
            #pragma unroll
            for (int i = 0; i < 4; i++)
                #pragma unroll
                for (int c = 0; c < 4; c++)
                    s[i][c] = fmaf(a[i], bb[c], s[i][c]);
        }

        if (j == qi) {  // diagonal tile: causal mask
            #pragma unroll
            for (int i = 0; i < 4; i++)
                #pragma unroll
                for (int c = 0; c < 4; c++)
                    if (tx * 4 + c > ty * 4 + i) s[i][c] = -1e30f;
        }

        // online softmax per row (16 lanes per row share m/l via xor-shuffles)
        #pragma unroll
        for (int i = 0; i < 4; i++) {
            float mx = fmaxf(fmaxf(s[i][0], s[i][1]), fmaxf(s[i][2], s[i][3]));
            #pragma unroll
            for (int off = 8; off > 0; off >>= 1)
                mx = fmaxf(mx, __shfl_xor_sync(0xffffffffu, mx, off));
            float mnew = fmaxf(mrow[i], mx);
            float psum = 0.0f;
            float p[4];
            #pragma unroll
            for (int c = 0; c < 4; c++) { p[c] = __expf(s[i][c] - mnew); psum += p[c]; }
            #pragma unroll
            for (int off = 8; off > 0; off >>= 1)
                psum += __shfl_xor_sync(0xffffffffu, psum, off);
            float fac = __expf(mrow[i] - mnew);
            lrow[i] = lrow[i] * fac + psum;
            mrow[i] = mnew;
            #pragma unroll
            for (int c = 0; c < 4; c++) o[i][c] *= fac;
            #pragma unroll
            for (int c = 0; c < 4; c++) Ps[(ty * 4 + i) * AS_ + tx * 4 + c] = p[c];
        }
        __syncthreads();

        // O += P @ V
        #pragma unroll 8
        for (int kk = 0; kk < 64; kk++) {
            float a[4], bb[4];
            #pragma unroll
            for (int i = 0; i < 4; i++) a[i]  = Ps[(ty * 4 + i) * AS_ + kk];
            #pragma unroll
            for (int c = 0; c < 4; c++) bb[c] = Vs[kk * AS_ + tx * 4 + c];
            #pragma unroll
            for (int i = 0; i < 4; i++)
                #pragma unroll
                for (int c = 0; c < 4; c++)
                    o[i][c] = fmaf(a[i], bb[c], o[i][c]);
        }
        __syncthreads();
    }

    // write y in [B, T, C] layout (fuses the transpose for the proj GEMM)
    #pragma unroll
    for (int i = 0; i < 4; i++) {
        int t = qi * 64 + ty * 4 + i;
        float inv_l = 1.0f / lrow[i];
        #pragma unroll
        for (int c = 0; c < 4; c++)
            g_y[((size_t)(b * T_ + t)) * C_ + h * D_ + tx * 4 + c] = o[i][c] * inv_l;
    }
}

// ---------------------------------------------------------------------------
// Proj GEMM: y[4096,1024] @ w_proj[1024,1024] + b_proj -> out
// ---------------------------------------------------------------------------
__global__ __launch_bounds__(256) void proj_kernel(
    const float* __restrict__ Bm, const float* __restrict__ bias,
    float* __restrict__ out)
{
    __shared__ float As[16][128];
    __shared__ float Bs[16][132];
    const int tid = threadIdx.x;
    const int tx = tid & 15, ty = tid >> 4;
    const int m0 = blockIdx.y * 128;
    const int n0 = blockIdx.x * 128;
    const float* A = g_y;

    float acc[8][8] = {};

    for (int kk = 0; kk < C_; kk += 16) {
        #pragma unroll
        for (int s = tid; s < 512; s += 256) {
            int arow = s >> 2, ac4 = (s & 3) << 2;
            float4 v = *(const float4*)(A + (size_t)(m0 + arow) * C_ + kk + ac4);
            As[ac4 + 0][arow] = v.x; As[ac4 + 1][arow] = v.y;
            As[ac4 + 2][arow] = v.z; As[ac4 + 3][arow] = v.w;
        }
        #pragma unroll
        for (int s = tid; s < 512; s += 256) {
            int brow = s >> 5, bc4 = (s & 31) << 2;
            *(float4*)&Bs[brow][bc4] =
                *(const float4*)(Bm + (size_t)(kk + brow) * C_ + n0 + bc4);
        }
        __syncthreads();
        #pragma unroll
        for (int k = 0; k < 16; k++) {
            float a[8], b[8];
            *(float4*)(a)     = *(const float4*)&As[k][ty * 8];
            *(float4*)(a + 4) = *(const float4*)&As[k][ty * 8 + 4];
            *(float4*)(b)     = *(const float4*)&Bs[k][tx * 8];
            *(float4*)(b + 4) = *(const float4*)&Bs[k][tx * 8 + 4];
            #pragma unroll
            for (int i = 0; i < 8; i++)
                #pragma unroll
                for (int j = 0; j < 8; j++)
                    acc[i][j] = fmaf(a[i], b[j], acc[i][j]);
        }
        __syncthreads();
    }

    #pragma unroll
    for (int i = 0; i < 8; i++) {
        int m = m0 + ty * 8 + i;
        #pragma unroll
        for (int j4 = 0; j4 < 8; j4 += 4) {
            int n = n0 + tx * 8 + j4;
            float4 bv = *(const float4*)(bias + n);
            float4 r;
            r.x = acc[i][j4 + 0] + bv.x;
            r.y = acc[i][j4 + 1] + bv.y;
            r.z = acc[i][j4 + 2] + bv.z;
            r.w = acc[i][j4 + 3] + bv.w;
            *(float4*)(out + (size_t)m * C_ + n) = r;
        }
    }
}

// ---------------------------------------------------------------------------
extern "C" void kernel_launch(void* const* d_in, const int* in_sizes, int n_in,
                              void* d_out, int out_size)
{
    const float* x      = (const float*)d_in[0];
    const float* w_qkv  = (const float*)d_in[1];
    const float* w_proj = (const float*)d_in[2];
    const float* b_proj = (const float*)d_in[3];
    float* out = (float*)d_out;

    (void)in_sizes; (void)n_in; (void)out_size;

    cudaFuncSetAttribute(attn_kernel,
                         cudaFuncAttributeMaxDynamicSharedMemorySize, ATTN_SMEM);

    rope_table_kernel<<<256, 256>>>();
    qkv_kernel<<<dim3(N3_ / 128, M_ / 128), 256>>>(x, w_qkv);
    attn_kernel<<<dim3(T_ / 64, BH_), 256, ATTN_SMEM>>>();
    proj_kernel<<<dim3(C_ / 128, M_ / 128), 256>>>(w_proj, b_proj, out);
}